// round 9
// baseline (speedup 1.0000x reference)
#include <cuda_runtime.h>
#include <cuda_bf16.h>

typedef unsigned long long ull;

#define DI static __device__ __forceinline__

// ---- packed f32x2 helpers (sm_100a) ----
DI ull ffma2(ull a, ull b, ull c) {
    ull d;
    asm("fma.rn.f32x2 %0, %1, %2, %3;" : "=l"(d) : "l"(a), "l"(b), "l"(c));
    return d;
}
DI ull fmul2(ull a, ull b) {
    ull d;
    asm("mul.rn.f32x2 %0, %1, %2;" : "=l"(d) : "l"(a), "l"(b));
    return d;
}
DI ull pack2(float lo, float hi) {
    ull d;
    asm("mov.b64 %0, {%1, %2};" : "=l"(d) : "f"(lo), "f"(hi));
    return d;
}
DI float2 unpack2(ull v) {
    float2 r;
    asm("mov.b64 {%0, %1}, %2;" : "=f"(r.x), "=f"(r.y) : "l"(v));
    return r;
}

constexpr int B = 2, T = 1024, D = 768, S = 128, HALF = 24;
constexpr int ROWS = B * D;            // 1536
constexpr int KSPLIT = 3, KSEG = 256;  // GEMM K split
constexpr int SEG = 4, L = 256;        // scan time segmentation (SEG*L = T)

// ---- device scratch (static: no allocation) ----
__device__ float g_xp[KSPLIT * ROWS * T];     // K-split partials of x@M, (row,t)
__device__ float g_f[ROWS * (SEG - 1) * S];   // per-(row,seg) local final states

// ============================================================
// GEMM: xp[ks][b*768+c][t] = sum_{k in seg ks} M[k,c] * x[b,t,k]
// 128x128 tile, 256 threads, 8x8 microtile via f32x2, double-buffered smem.
// ============================================================
__global__ void __launch_bounds__(256, 2) gemm_kernel(const float* __restrict__ x,
                                                      const float* __restrict__ Min) {
    const int cbase = blockIdx.x * 128;
    const int tbase = blockIdx.y * 128;
    const int b     = blockIdx.z / KSPLIT;
    const int ks    = blockIdx.z % KSPLIT;
    const int kbase = ks * KSEG;

    __shared__ float As[2][8][132];
    __shared__ float Bs[2][8][132];

    const int tid = threadIdx.x;
    const int a_k = tid >> 5;
    const int a_c = (tid & 31) << 2;
    const int b_t = tid >> 1;
    const int b_k = (tid & 1) << 2;
    const int tx = tid & 15;
    const int ty = tid >> 4;

    const float* Ap = Min + (size_t)(kbase + a_k) * D + cbase + a_c;
    const float* Bp = x + ((size_t)b * T + tbase + b_t) * D + kbase + b_k;

    ull acc[8][4];
#pragma unroll
    for (int i = 0; i < 8; i++)
#pragma unroll
        for (int j = 0; j < 4; j++) acc[i][j] = 0ull;

    {
        float4 av = *(const float4*)Ap;
        float4 bv = *(const float4*)Bp;
        *(float4*)&As[0][a_k][a_c] = av;
        Bs[0][b_k + 0][b_t] = bv.x;
        Bs[0][b_k + 1][b_t] = bv.y;
        Bs[0][b_k + 2][b_t] = bv.z;
        Bs[0][b_k + 3][b_t] = bv.w;
    }
    __syncthreads();

#pragma unroll 2
    for (int kt = 0; kt < KSEG / 8; kt++) {
        const int cur = kt & 1;
        float4 av, bv;
        const bool more = (kt + 1 < KSEG / 8);
        if (more) {
            Ap += 8 * D;
            Bp += 8;
            av = *(const float4*)Ap;
            bv = *(const float4*)Bp;
        }
#pragma unroll
        for (int kk = 0; kk < 8; kk++) {
            float4 af0 = *(const float4*)&As[cur][kk][ty * 8];
            float4 af1 = *(const float4*)&As[cur][kk][ty * 8 + 4];
            ull b20 = *(const ull*)&Bs[cur][kk][tx * 8];
            ull b21 = *(const ull*)&Bs[cur][kk][tx * 8 + 2];
            ull b22 = *(const ull*)&Bs[cur][kk][tx * 8 + 4];
            ull b23 = *(const ull*)&Bs[cur][kk][tx * 8 + 6];
            float a[8] = {af0.x, af0.y, af0.z, af0.w, af1.x, af1.y, af1.z, af1.w};
#pragma unroll
            for (int i = 0; i < 8; i++) {
                ull ai = pack2(a[i], a[i]);
                acc[i][0] = ffma2(ai, b20, acc[i][0]);
                acc[i][1] = ffma2(ai, b21, acc[i][1]);
                acc[i][2] = ffma2(ai, b22, acc[i][2]);
                acc[i][3] = ffma2(ai, b23, acc[i][3]);
            }
        }
        if (more) {
            const int nxt = cur ^ 1;
            *(float4*)&As[nxt][a_k][a_c] = av;
            Bs[nxt][b_k + 0][b_t] = bv.x;
            Bs[nxt][b_k + 1][b_t] = bv.y;
            Bs[nxt][b_k + 2][b_t] = bv.z;
            Bs[nxt][b_k + 3][b_t] = bv.w;
            __syncthreads();
        }
    }

    float* outbase = g_xp + (size_t)ks * ROWS * T;
#pragma unroll
    for (int i = 0; i < 8; i++) {
        int row = b * D + cbase + ty * 8 + i;
        float* dst = outbase + (size_t)row * T + tbase + tx * 8;
        float2 p0 = unpack2(acc[i][0]);
        float2 p1 = unpack2(acc[i][1]);
        float2 p2 = unpack2(acc[i][2]);
        float2 p3 = unpack2(acc[i][3]);
        *(float4*)dst       = make_float4(p0.x, p0.y, p1.x, p1.y);
        *(float4*)(dst + 4) = make_float4(p2.x, p2.y, p3.x, p3.y);
    }
}

// ============================================================
// Scan pass 1: recurrence only, segments 0..2. One warp per (row,seg).
// Lane owns states {2l,2l+1} and {64+2l,64+2l+1} as f32x2 pairs.
// Stores local final state F (h starting from 0) to g_f.
// ============================================================
__global__ void __launch_bounds__(256) scan_pass1(const float* __restrict__ Ain) {
    const int warp = threadIdx.x >> 5;
    const int lane = threadIdx.x & 31;
    const int row = blockIdx.x * 8 + warp;  // 0..1535
    const int seg = blockIdx.y;             // 0..SEG-2

    ull A20 = *(const ull*)(Ain + 2 * lane);
    ull A21 = *(const ull*)(Ain + 64 + 2 * lane);

    const float* x0 = g_xp + (size_t)row * T;
    const float* x1 = x0 + (size_t)ROWS * T;
    const float* x2 = x1 + (size_t)ROWS * T;
    const int tb = seg * L;

    ull h0 = 0ull, h1 = 0ull;

    float xv = x0[tb + lane] + x1[tb + lane] + x2[tb + lane];
    for (int t0 = 0; t0 < L; t0 += 32) {
        float cur = xv;
        if (t0 + 32 < L) {
            int t = tb + t0 + 32 + lane;
            xv = x0[t] + x1[t] + x2[t];
        }
#pragma unroll
        for (int tt = 0; tt < 32; tt++) {
            float xs = __shfl_sync(0xffffffffu, cur, tt);
            ull xx = pack2(xs, xs);
            h0 = ffma2(A20, h0, xx);
            h1 = ffma2(A21, h1, xx);
        }
    }

    ull* f = (ull*)(g_f + ((size_t)row * (SEG - 1) + seg) * S);
    f[lane] = h0;        // floats 2l, 2l+1
    f[32 + lane] = h1;   // floats 64+2l, 64+2l+1
}

// ============================================================
// Scan pass 2: full scan with readout per (row,seg). CTA = 8 warps =
// 8 consecutive rows (same batch), one segment. h_start reconstructed
// locally: AL = A^256 via 8 squarings, prefix over g_f (<= 3 FMAs).
// W computed inline. Output written coalesced on the bf16 grid.
// ============================================================
__global__ void __launch_bounds__(256) scan_pass2(const float* __restrict__ Ain,
                                                  const float* __restrict__ BC,
                                                  const float* __restrict__ Mfil,
                                                  float* __restrict__ out) {
    __shared__ float sp[8][32 * 33];
    __shared__ float ys[2][32][9];

    const int tid = threadIdx.x;
    const int warp = tid >> 5;
    const int lane = tid & 31;
    const int group = blockIdx.x;           // 0..191 (8-row group)
    const int seg = blockIdx.y;             // 0..3
    const int row = group * 8 + warp;
    const int b = row / D;
    const int c = row % D;
    const int c0 = (group * 8) % D;

    ull A20 = *(const ull*)(Ain + 2 * lane);
    ull A21 = *(const ull*)(Ain + 64 + 2 * lane);

    // ---- inline W: W[s,c] = sum_k (BC[s,k]+BC[s,k+24]) * Mfil[k,c] ----
    float w0 = 0.f, w1 = 0.f, w2 = 0.f, w3 = 0.f;
    {
        const int s0 = 2 * lane, s2 = 64 + 2 * lane;
        const float* bc0 = BC + s0 * 2 * HALF;
        const float* bc1 = BC + (s0 + 1) * 2 * HALF;
        const float* bc2 = BC + s2 * 2 * HALF;
        const float* bc3 = BC + (s2 + 1) * 2 * HALF;
#pragma unroll
        for (int k = 0; k < HALF; k++) {
            float mf = Mfil[k * D + c];  // lane-invariant broadcast
            w0 = fmaf(bc0[k] + bc0[HALF + k], mf, w0);
            w1 = fmaf(bc1[k] + bc1[HALF + k], mf, w1);
            w2 = fmaf(bc2[k] + bc2[HALF + k], mf, w2);
            w3 = fmaf(bc3[k] + bc3[HALF + k], mf, w3);
        }
    }
    ull W20 = pack2(w0, w1);
    ull W21 = pack2(w2, w3);

    // ---- h_start: AL = A^256 (8 squarings), prefix over local finals ----
    ull h0 = 0ull, h1 = 0ull;
    if (seg > 0) {
        ull al0 = A20, al1 = A21;
#pragma unroll
        for (int q = 0; q < 8; q++) {
            al0 = fmul2(al0, al0);
            al1 = fmul2(al1, al1);
        }
        const ull* f = (const ull*)(g_f + (size_t)row * (SEG - 1) * S);
        for (int j = 0; j < seg; j++) {
            h0 = ffma2(al0, h0, f[(size_t)j * 64 + lane]);
            h1 = ffma2(al1, h1, f[(size_t)j * 64 + 32 + lane]);
        }
    }

    const float* x0 = g_xp + (size_t)row * T;
    const float* x1 = x0 + (size_t)ROWS * T;
    const float* x2 = x1 + (size_t)ROWS * T;
    const int tb = seg * L;

    float* spm = sp[warp];

    float xv = x0[tb + lane] + x1[tb + lane] + x2[tb + lane];
    for (int t0 = 0; t0 < L; t0 += 32) {
        float cur = xv;
        if (t0 + 32 < L) {
            int t = tb + t0 + 32 + lane;
            xv = x0[t] + x1[t] + x2[t];
        }
#pragma unroll
        for (int tt = 0; tt < 32; tt++) {
            float xs = __shfl_sync(0xffffffffu, cur, tt);
            ull xx = pack2(xs, xs);
            h0 = ffma2(A20, h0, xx);
            h1 = ffma2(A21, h1, xx);
            ull p = fmul2(h0, W20);
            p = ffma2(h1, W21, p);
            float2 pf = unpack2(p);
            spm[tt * 33 + lane] = pf.x + pf.y;  // conflict-free
        }
        __syncwarp();
        // lane j reduces time index j over the 32 source lanes
        const float* col = spm + lane * 33;
        float a0 = 0.f, a1 = 0.f, a2 = 0.f, a3 = 0.f;
#pragma unroll
        for (int l = 0; l < 32; l += 4) {
            a0 += col[l];
            a1 += col[l + 1];
            a2 += col[l + 2];
            a3 += col[l + 3];
        }
        const int buf = (t0 >> 5) & 1;
        ys[buf][lane][warp] = (a0 + a1) + (a2 + a3);
        __syncthreads();
        const int ti = tid >> 3, ci = tid & 7;
        float v = ys[buf][ti][ci];
        out[((size_t)b * T + tb + t0 + ti) * D + c0 + ci] =
            __bfloat162float(__float2bfloat16(v));
    }
}

// ============================================================
extern "C" void kernel_launch(void* const* d_in, const int* in_sizes, int n_in,
                              void* d_out, int out_size) {
    const float* x = nullptr;
    const float *Min = nullptr, *Mfil = nullptr, *A = nullptr, *BC = nullptr;
    for (int i = 0; i < n_in; i++) {
        switch (in_sizes[i]) {  // all five element counts are distinct
            case B * T * D:     x    = (const float*)d_in[i]; break;  // 1572864
            case D * D:         Min  = (const float*)d_in[i]; break;  // 589824
            case HALF * D:      Mfil = (const float*)d_in[i]; break;  // 18432
            case S:             A    = (const float*)d_in[i]; break;  // 128
            case S * 2 * HALF:  BC   = (const float*)d_in[i]; break;  // 6144
        }
    }

    gemm_kernel<<<dim3(D / 128, T / 128, B * KSPLIT), 256>>>(x, Min);
    scan_pass1<<<dim3(ROWS / 8, SEG - 1), 256>>>(A);
    scan_pass2<<<dim3(ROWS / 8 / 1, SEG) /* 192 x 4 */, 256>>>(A, BC, Mfil, (float*)d_out);
}

// round 11
// speedup vs baseline: 2.0513x; 2.0513x over previous
#include <cuda_runtime.h>
#include <cuda_bf16.h>

typedef unsigned long long ull;

#define DI static __device__ __forceinline__

// ---- packed f32x2 helpers (sm_100a) ----
DI ull ffma2(ull a, ull b, ull c) {
    ull d;
    asm("fma.rn.f32x2 %0, %1, %2, %3;" : "=l"(d) : "l"(a), "l"(b), "l"(c));
    return d;
}
DI ull fmul2(ull a, ull b) {
    ull d;
    asm("mul.rn.f32x2 %0, %1, %2;" : "=l"(d) : "l"(a), "l"(b));
    return d;
}
DI ull pack2(float lo, float hi) {
    ull d;
    asm("mov.b64 %0, {%1, %2};" : "=l"(d) : "f"(lo), "f"(hi));
    return d;
}
DI float2 unpack2(ull v) {
    float2 r;
    asm("mov.b64 {%0, %1}, %2;" : "=f"(r.x), "=f"(r.y) : "l"(v));
    return r;
}

constexpr int B = 2, T = 1024, D = 768, S = 128, HALF = 24;
constexpr int ROWS = B * D;            // 1536
constexpr int KSPLIT = 3, KSEG = 256;  // 3 * 256 = 768 = K

// ---- device scratch (static: no allocation) ----
__device__ float g_Wt[D * S];               // W^T: Wt[c*S+s]
__device__ float g_xp[KSPLIT * ROWS * T];   // K-split partials of x@M, (row,t)
__device__ float g_yp[ROWS * T];            // scan output, (row,t)

// ============================================================
// W[s,c] = sum_k (BC[s,k] + BC[s,k+24]) * M_filters[k,c], stored Wt[c*S+s]
// grid (S, 3), block 256 -> 384 CTAs
// ============================================================
__global__ void prep_w(const float* __restrict__ BC, const float* __restrict__ Mfil) {
    int s = blockIdx.x;                          // 0..127
    int c = blockIdx.y * 256 + threadIdx.x;      // 0..767
    float acc = 0.f;
#pragma unroll
    for (int k = 0; k < HALF; k++) {
        float bsum = BC[s * 2 * HALF + k] + BC[s * 2 * HALF + HALF + k];
        acc = fmaf(bsum, Mfil[k * D + c], acc);
    }
    g_Wt[(size_t)c * S + s] = acc;
}

// ============================================================
// GEMM: xp[ks][b*768+c][t] = sum_{k in seg ks} M[k,c] * x[b,t,k]
// 128x128 tile, 256 threads, 8x8 microtile via f32x2, double-buffered smem.
// A-tile stored PRE-DUPLICATED as (a,a) pairs: inner loop is pure
// LDS.128 + FFMA2 (no pack MOVs).
// ============================================================
__global__ void __launch_bounds__(256, 2) gemm_kernel(const float* __restrict__ x,
                                                      const float* __restrict__ Min) {
    const int cbase = blockIdx.x * 128;
    const int tbase = blockIdx.y * 128;
    const int b     = blockIdx.z / KSPLIT;
    const int ks    = blockIdx.z % KSPLIT;
    const int kbase = ks * KSEG;

    __shared__ float As2[2][8][264];  // duplicated pairs: pair c holds (a_c,a_c)
    __shared__ float Bs[2][8][132];

    const int tid = threadIdx.x;
    const int a_k = tid >> 5;
    const int a_c = (tid & 31) << 2;   // float column base (4 per thread)
    const int b_t = tid >> 1;
    const int b_k = (tid & 1) << 2;
    const int tx = tid & 15;
    const int ty = tid >> 4;

    const float* Ap = Min + (size_t)(kbase + a_k) * D + cbase + a_c;
    const float* Bp = x + ((size_t)b * T + tbase + b_t) * D + kbase + b_k;

    ull acc[8][4];
#pragma unroll
    for (int i = 0; i < 8; i++)
#pragma unroll
        for (int j = 0; j < 4; j++) acc[i][j] = 0ull;

    // prologue: fill buffer 0
    {
        float4 av = *(const float4*)Ap;
        float4 bv = *(const float4*)Bp;
        *(float4*)&As2[0][a_k][2 * a_c]     = make_float4(av.x, av.x, av.y, av.y);
        *(float4*)&As2[0][a_k][2 * a_c + 4] = make_float4(av.z, av.z, av.w, av.w);
        Bs[0][b_k + 0][b_t] = bv.x;
        Bs[0][b_k + 1][b_t] = bv.y;
        Bs[0][b_k + 2][b_t] = bv.z;
        Bs[0][b_k + 3][b_t] = bv.w;
    }
    __syncthreads();

#pragma unroll 2
    for (int kt = 0; kt < KSEG / 8; kt++) {
        const int cur = kt & 1;
        float4 av, bv;
        const bool more = (kt + 1 < KSEG / 8);
        if (more) {
            Ap += 8 * D;
            Bp += 8;
            av = *(const float4*)Ap;
            bv = *(const float4*)Bp;
        }
#pragma unroll
        for (int kk = 0; kk < 8; kk++) {
            const ull* arow = (const ull*)&As2[cur][kk][2 * (ty * 8)];
            ull a2[8];
#pragma unroll
            for (int i = 0; i < 8; i++) a2[i] = arow[i];
            ull b20 = *(const ull*)&Bs[cur][kk][tx * 8];
            ull b21 = *(const ull*)&Bs[cur][kk][tx * 8 + 2];
            ull b22 = *(const ull*)&Bs[cur][kk][tx * 8 + 4];
            ull b23 = *(const ull*)&Bs[cur][kk][tx * 8 + 6];
#pragma unroll
            for (int i = 0; i < 8; i++) {
                acc[i][0] = ffma2(a2[i], b20, acc[i][0]);
                acc[i][1] = ffma2(a2[i], b21, acc[i][1]);
                acc[i][2] = ffma2(a2[i], b22, acc[i][2]);
                acc[i][3] = ffma2(a2[i], b23, acc[i][3]);
            }
        }
        if (more) {
            const int nxt = cur ^ 1;
            *(float4*)&As2[nxt][a_k][2 * a_c]     = make_float4(av.x, av.x, av.y, av.y);
            *(float4*)&As2[nxt][a_k][2 * a_c + 4] = make_float4(av.z, av.z, av.w, av.w);
            Bs[nxt][b_k + 0][b_t] = bv.x;
            Bs[nxt][b_k + 1][b_t] = bv.y;
            Bs[nxt][b_k + 2][b_t] = bv.z;
            Bs[nxt][b_k + 3][b_t] = bv.w;
            __syncthreads();
        }
    }

    float* outbase = g_xp + (size_t)ks * ROWS * T;
#pragma unroll
    for (int i = 0; i < 8; i++) {
        int row = b * D + cbase + ty * 8 + i;
        float* dst = outbase + (size_t)row * T + tbase + tx * 8;
        float2 p0 = unpack2(acc[i][0]);
        float2 p1 = unpack2(acc[i][1]);
        float2 p2 = unpack2(acc[i][2]);
        float2 p3 = unpack2(acc[i][3]);
        *(float4*)dst       = make_float4(p0.x, p0.y, p1.x, p1.y);
        *(float4*)(dst + 4) = make_float4(p2.x, p2.y, p3.x, p3.y);
    }
}

// ============================================================
// Scan — EXACT R7 structure (empirically fastest): one warp per row,
// 4 warps/CTA, 384 CTAs. Lane owns 4 states as two f32x2 pairs. x staged
// in smem, per-step partials staged in smem, transpose-reduce per 32 steps.
// ============================================================
constexpr int SCAN_WARPS = 4;

__global__ void __launch_bounds__(SCAN_WARPS * 32) scan_kernel(const float* __restrict__ Ain) {
    __shared__ float sx[SCAN_WARPS][32];
    __shared__ float sp[SCAN_WARPS][32 * 33];

    const int warp = threadIdx.x >> 5;
    const int lane = threadIdx.x & 31;
    const int row = blockIdx.x * SCAN_WARPS + warp;  // 0..1535
    const int c = row % D;

    ull A20 = *(const ull*)(Ain + 2 * lane);
    ull A21 = *(const ull*)(Ain + 64 + 2 * lane);
    const float* Wr = g_Wt + (size_t)c * S;
    ull W20 = *(const ull*)(Wr + 2 * lane);
    ull W21 = *(const ull*)(Wr + 64 + 2 * lane);

    const float* x0 = g_xp + (size_t)row * T;
    const float* x1 = x0 + (size_t)ROWS * T;
    const float* x2 = x1 + (size_t)ROWS * T;
    float* yr = g_yp + (size_t)row * T;

    float* sxm = sx[warp];
    float* spm = sp[warp];

    ull h0 = 0ull, h1 = 0ull;

    float xv = x0[lane] + x1[lane] + x2[lane];  // sum K-split partials
    for (int t0 = 0; t0 < T; t0 += 32) {
        sxm[lane] = xv;
        __syncwarp();
        if (t0 + 32 < T) {  // prefetch next block
            int t = t0 + 32 + lane;
            xv = x0[t] + x1[t] + x2[t];
        }
#pragma unroll
        for (int tt = 0; tt < 32; tt++) {
            float xs = sxm[tt];
            ull xx = pack2(xs, xs);
            h0 = ffma2(A20, h0, xx);
            h1 = ffma2(A21, h1, xx);
            ull p = fmul2(h0, W20);
            p = ffma2(h1, W21, p);
            float2 pf = unpack2(p);
            spm[tt * 33 + lane] = pf.x + pf.y;  // conflict-free
        }
        __syncwarp();
        const float* col = spm + lane * 33;
        float a0 = 0.f, a1 = 0.f, a2 = 0.f, a3 = 0.f;
#pragma unroll
        for (int l = 0; l < 32; l += 4) {
            a0 += col[l];
            a1 += col[l + 1];
            a2 += col[l + 2];
            a3 += col[l + 3];
        }
        yr[t0 + lane] = (a0 + a1) + (a2 + a3);
        __syncwarp();
    }
}

// ============================================================
// Transpose (row,t) fp32 -> (b,t,c), output f32 on bf16 grid
// ============================================================
__global__ void transpose_kernel(float* __restrict__ out) {
    __shared__ float tile[32][33];
    const int t0 = blockIdx.x * 32;
    const int c0 = blockIdx.y * 32;
    const int b = blockIdx.z;
    const int tx = threadIdx.x, ty = threadIdx.y;
#pragma unroll
    for (int i = 0; i < 32; i += 8)
        tile[ty + i][tx] = g_yp[(size_t)(b * D + c0 + ty + i) * T + t0 + tx];
    __syncthreads();
#pragma unroll
    for (int i = 0; i < 32; i += 8) {
        float v = tile[tx][ty + i];
        out[(size_t)(b * T + t0 + ty + i) * D + c0 + tx] =
            __bfloat162float(__float2bfloat16(v));
    }
}

// ============================================================
extern "C" void kernel_launch(void* const* d_in, const int* in_sizes, int n_in,
                              void* d_out, int out_size) {
    const float* x = nullptr;
    const float *Min = nullptr, *Mfil = nullptr, *A = nullptr, *BC = nullptr;
    for (int i = 0; i < n_in; i++) {
        switch (in_sizes[i]) {  // all five element counts are distinct
            case B * T * D:     x    = (const float*)d_in[i]; break;  // 1572864
            case D * D:         Min  = (const float*)d_in[i]; break;  // 589824
            case HALF * D:      Mfil = (const float*)d_in[i]; break;  // 18432
            case S:             A    = (const float*)d_in[i]; break;  // 128
            case S * 2 * HALF:  BC   = (const float*)d_in[i]; break;  // 6144
        }
    }

    prep_w<<<dim3(S, 3), 256>>>(BC, Mfil);
    gemm_kernel<<<dim3(D / 128, T / 128, B * KSPLIT), 256>>>(x, Min);
    scan_kernel<<<ROWS / SCAN_WARPS, SCAN_WARPS * 32>>>(A);
    transpose_kernel<<<dim3(T / 32, D / 32, B), dim3(32, 8)>>>((float*)d_out);
}

// round 12
// speedup vs baseline: 2.2371x; 1.0906x over previous
#include <cuda_runtime.h>
#include <cuda_bf16.h>

typedef unsigned long long ull;

#define DI static __device__ __forceinline__

// ---- packed f32x2 helpers (sm_100a) ----
DI ull ffma2(ull a, ull b, ull c) {
    ull d;
    asm("fma.rn.f32x2 %0, %1, %2, %3;" : "=l"(d) : "l"(a), "l"(b), "l"(c));
    return d;
}
DI ull fmul2(ull a, ull b) {
    ull d;
    asm("mul.rn.f32x2 %0, %1, %2;" : "=l"(d) : "l"(a), "l"(b));
    return d;
}
DI ull pack2(float lo, float hi) {
    ull d;
    asm("mov.b64 %0, {%1, %2};" : "=l"(d) : "f"(lo), "f"(hi));
    return d;
}
DI float2 unpack2(ull v) {
    float2 r;
    asm("mov.b64 {%0, %1}, %2;" : "=f"(r.x), "=f"(r.y) : "l"(v));
    return r;
}

constexpr int B = 2, T = 1024, D = 768, S = 128, HALF = 24;
constexpr int ROWS = B * D;            // 1536
constexpr int KSPLIT = 3, KSEG = 256;  // 3 * 256 = 768 = K

// ---- device scratch (static: no allocation) ----
__device__ float g_Wt[D * S];               // W^T: Wt[c*S+s]
__device__ float g_xp[KSPLIT * ROWS * T];   // K-split partials of x@M, (row,t)
__device__ float g_yp[ROWS * T];            // scan output, (row,t)

// ============================================================
// W[s,c] = sum_k (BC[s,k] + BC[s,k+24]) * M_filters[k,c], stored Wt[c*S+s]
// grid (S, 3), block 256 -> 384 CTAs
// ============================================================
__global__ void prep_w(const float* __restrict__ BC, const float* __restrict__ Mfil) {
    int s = blockIdx.x;                          // 0..127
    int c = blockIdx.y * 256 + threadIdx.x;      // 0..767
    float acc = 0.f;
#pragma unroll
    for (int k = 0; k < HALF; k++) {
        float bsum = BC[s * 2 * HALF + k] + BC[s * 2 * HALF + HALF + k];
        acc = fmaf(bsum, Mfil[k * D + c], acc);
    }
    g_Wt[(size_t)c * S + s] = acc;
}

// ============================================================
// GEMM — R9 version VERBATIM (measured 63.8 us):
// 128x128 tile, 256 threads, 8x8 microtile via f32x2 (pack2 in inner loop),
// double-buffered smem, K split into 3 segments -> 288 CTAs.
// ============================================================
__global__ void __launch_bounds__(256, 2) gemm_kernel(const float* __restrict__ x,
                                                      const float* __restrict__ Min) {
    const int cbase = blockIdx.x * 128;
    const int tbase = blockIdx.y * 128;
    const int b     = blockIdx.z / KSPLIT;
    const int ks    = blockIdx.z % KSPLIT;
    const int kbase = ks * KSEG;

    __shared__ float As[2][8][132];
    __shared__ float Bs[2][8][132];

    const int tid = threadIdx.x;
    const int a_k = tid >> 5;
    const int a_c = (tid & 31) << 2;
    const int b_t = tid >> 1;
    const int b_k = (tid & 1) << 2;
    const int tx = tid & 15;
    const int ty = tid >> 4;

    const float* Ap = Min + (size_t)(kbase + a_k) * D + cbase + a_c;
    const float* Bp = x + ((size_t)b * T + tbase + b_t) * D + kbase + b_k;

    ull acc[8][4];
#pragma unroll
    for (int i = 0; i < 8; i++)
#pragma unroll
        for (int j = 0; j < 4; j++) acc[i][j] = 0ull;

    {
        float4 av = *(const float4*)Ap;
        float4 bv = *(const float4*)Bp;
        *(float4*)&As[0][a_k][a_c] = av;
        Bs[0][b_k + 0][b_t] = bv.x;
        Bs[0][b_k + 1][b_t] = bv.y;
        Bs[0][b_k + 2][b_t] = bv.z;
        Bs[0][b_k + 3][b_t] = bv.w;
    }
    __syncthreads();

#pragma unroll 2
    for (int kt = 0; kt < KSEG / 8; kt++) {
        const int cur = kt & 1;
        float4 av, bv;
        const bool more = (kt + 1 < KSEG / 8);
        if (more) {
            Ap += 8 * D;
            Bp += 8;
            av = *(const float4*)Ap;
            bv = *(const float4*)Bp;
        }
#pragma unroll
        for (int kk = 0; kk < 8; kk++) {
            float4 af0 = *(const float4*)&As[cur][kk][ty * 8];
            float4 af1 = *(const float4*)&As[cur][kk][ty * 8 + 4];
            ull b20 = *(const ull*)&Bs[cur][kk][tx * 8];
            ull b21 = *(const ull*)&Bs[cur][kk][tx * 8 + 2];
            ull b22 = *(const ull*)&Bs[cur][kk][tx * 8 + 4];
            ull b23 = *(const ull*)&Bs[cur][kk][tx * 8 + 6];
            float a[8] = {af0.x, af0.y, af0.z, af0.w, af1.x, af1.y, af1.z, af1.w};
#pragma unroll
            for (int i = 0; i < 8; i++) {
                ull ai = pack2(a[i], a[i]);
                acc[i][0] = ffma2(ai, b20, acc[i][0]);
                acc[i][1] = ffma2(ai, b21, acc[i][1]);
                acc[i][2] = ffma2(ai, b22, acc[i][2]);
                acc[i][3] = ffma2(ai, b23, acc[i][3]);
            }
        }
        if (more) {
            const int nxt = cur ^ 1;
            *(float4*)&As[nxt][a_k][a_c] = av;
            Bs[nxt][b_k + 0][b_t] = bv.x;
            Bs[nxt][b_k + 1][b_t] = bv.y;
            Bs[nxt][b_k + 2][b_t] = bv.z;
            Bs[nxt][b_k + 3][b_t] = bv.w;
            __syncthreads();
        }
    }

    float* outbase = g_xp + (size_t)ks * ROWS * T;
#pragma unroll
    for (int i = 0; i < 8; i++) {
        int row = b * D + cbase + ty * 8 + i;
        float* dst = outbase + (size_t)row * T + tbase + tx * 8;
        float2 p0 = unpack2(acc[i][0]);
        float2 p1 = unpack2(acc[i][1]);
        float2 p2 = unpack2(acc[i][2]);
        float2 p3 = unpack2(acc[i][3]);
        *(float4*)dst       = make_float4(p0.x, p0.y, p1.x, p1.y);
        *(float4*)(dst + 4) = make_float4(p2.x, p2.y, p3.x, p3.y);
    }
}

// ============================================================
// Scan — R7 structure VERBATIM (empirically fastest): one warp per row,
// 4 warps/CTA, 384 CTAs. Lane owns 4 states as two f32x2 pairs. x staged
// in smem, per-step partials staged in smem, transpose-reduce per 32 steps.
// ============================================================
constexpr int SCAN_WARPS = 4;

__global__ void __launch_bounds__(SCAN_WARPS * 32) scan_kernel(const float* __restrict__ Ain) {
    __shared__ float sx[SCAN_WARPS][32];
    __shared__ float sp[SCAN_WARPS][32 * 33];

    const int warp = threadIdx.x >> 5;
    const int lane = threadIdx.x & 31;
    const int row = blockIdx.x * SCAN_WARPS + warp;  // 0..1535
    const int c = row % D;

    ull A20 = *(const ull*)(Ain + 2 * lane);
    ull A21 = *(const ull*)(Ain + 64 + 2 * lane);
    const float* Wr = g_Wt + (size_t)c * S;
    ull W20 = *(const ull*)(Wr + 2 * lane);
    ull W21 = *(const ull*)(Wr + 64 + 2 * lane);

    const float* x0 = g_xp + (size_t)row * T;
    const float* x1 = x0 + (size_t)ROWS * T;
    const float* x2 = x1 + (size_t)ROWS * T;
    float* yr = g_yp + (size_t)row * T;

    float* sxm = sx[warp];
    float* spm = sp[warp];

    ull h0 = 0ull, h1 = 0ull;

    float xv = x0[lane] + x1[lane] + x2[lane];  // sum K-split partials
    for (int t0 = 0; t0 < T; t0 += 32) {
        sxm[lane] = xv;
        __syncwarp();
        if (t0 + 32 < T) {  // prefetch next block
            int t = t0 + 32 + lane;
            xv = x0[t] + x1[t] + x2[t];
        }
#pragma unroll
        for (int tt = 0; tt < 32; tt++) {
            float xs = sxm[tt];
            ull xx = pack2(xs, xs);
            h0 = ffma2(A20, h0, xx);
            h1 = ffma2(A21, h1, xx);
            ull p = fmul2(h0, W20);
            p = ffma2(h1, W21, p);
            float2 pf = unpack2(p);
            spm[tt * 33 + lane] = pf.x + pf.y;  // conflict-free
        }
        __syncwarp();
        const float* col = spm + lane * 33;
        float a0 = 0.f, a1 = 0.f, a2 = 0.f, a3 = 0.f;
#pragma unroll
        for (int l = 0; l < 32; l += 4) {
            a0 += col[l];
            a1 += col[l + 1];
            a2 += col[l + 2];
            a3 += col[l + 3];
        }
        yr[t0 + lane] = (a0 + a1) + (a2 + a3);
        __syncwarp();
    }
}

// ============================================================
// Transpose (row,t) fp32 -> (b,t,c), output f32 on bf16 grid
// ============================================================
__global__ void transpose_kernel(float* __restrict__ out) {
    __shared__ float tile[32][33];
    const int t0 = blockIdx.x * 32;
    const int c0 = blockIdx.y * 32;
    const int b = blockIdx.z;
    const int tx = threadIdx.x, ty = threadIdx.y;
#pragma unroll
    for (int i = 0; i < 32; i += 8)
        tile[ty + i][tx] = g_yp[(size_t)(b * D + c0 + ty + i) * T + t0 + tx];
    __syncthreads();
#pragma unroll
    for (int i = 0; i < 32; i += 8) {
        float v = tile[tx][ty + i];
        out[(size_t)(b * T + t0 + ty + i) * D + c0 + tx] =
            __bfloat162float(__float2bfloat16(v));
    }
}

// ============================================================
extern "C" void kernel_launch(void* const* d_in, const int* in_sizes, int n_in,
                              void* d_out, int out_size) {
    const float* x = nullptr;
    const float *Min = nullptr, *Mfil = nullptr, *A = nullptr, *BC = nullptr;
    for (int i = 0; i < n_in; i++) {
        switch (in_sizes[i]) {  // all five element counts are distinct
            case B * T * D:     x    = (const float*)d_in[i]; break;  // 1572864
            case D * D:         Min  = (const float*)d_in[i]; break;  // 589824
            case HALF * D:      Mfil = (const float*)d_in[i]; break;  // 18432
            case S:             A    = (const float*)d_in[i]; break;  // 128
            case S * 2 * HALF:  BC   = (const float*)d_in[i]; break;  // 6144
        }
    }

    prep_w<<<dim3(S, 3), 256>>>(BC, Mfil);
    gemm_kernel<<<dim3(D / 128, T / 128, B * KSPLIT), 256>>>(x, Min);
    scan_kernel<<<ROWS / SCAN_WARPS, SCAN_WARPS * 32>>>(A);
    transpose_kernel<<<dim3(T / 32, D / 32, B), dim3(32, 8)>>>((float*)d_out);
}

// round 13
// speedup vs baseline: 2.4593x; 1.0993x over previous
#include <cuda_runtime.h>
#include <cuda_bf16.h>

typedef unsigned long long ull;

#define DI static __device__ __forceinline__

// ---- packed f32x2 helpers (sm_100a) ----
DI ull ffma2(ull a, ull b, ull c) {
    ull d;
    asm("fma.rn.f32x2 %0, %1, %2, %3;" : "=l"(d) : "l"(a), "l"(b), "l"(c));
    return d;
}
DI ull fmul2(ull a, ull b) {
    ull d;
    asm("mul.rn.f32x2 %0, %1, %2;" : "=l"(d) : "l"(a), "l"(b));
    return d;
}
DI ull pack2(float lo, float hi) {
    ull d;
    asm("mov.b64 %0, {%1, %2};" : "=l"(d) : "f"(lo), "f"(hi));
    return d;
}
DI float2 unpack2(ull v) {
    float2 r;
    asm("mov.b64 {%0, %1}, %2;" : "=f"(r.x), "=f"(r.y) : "l"(v));
    return r;
}

constexpr int B = 2, T = 1024, D = 768, S = 128, HALF = 24;
constexpr int ROWS = B * D;            // 1536
constexpr int KSPLIT = 3, KSEG = 256;  // 3 * 256 = 768 = K

// ---- device scratch (static: no allocation) ----
__device__ float g_Wt[D * S];               // W^T: Wt[c*S+s]
__device__ float g_xp[KSPLIT * ROWS * T];   // K-split partials of x@M, (row,t)
__device__ float g_yp[ROWS * T];            // scan output, (row,t)

// ============================================================
// W[s,c] = sum_k (BC[s,k] + BC[s,k+24]) * M_filters[k,c], stored Wt[c*S+s]
// ============================================================
__global__ void prep_w(const float* __restrict__ BC, const float* __restrict__ Mfil) {
    int s = blockIdx.x;                          // 0..127
    int c = blockIdx.y * 256 + threadIdx.x;      // 0..767
    float acc = 0.f;
#pragma unroll
    for (int k = 0; k < HALF; k++) {
        float bsum = BC[s * 2 * HALF + k] + BC[s * 2 * HALF + HALF + k];
        acc = fmaf(bsum, Mfil[k * D + c], acc);
    }
    g_Wt[(size_t)c * S + s] = acc;
}

// ============================================================
// GEMM: R9 double-buffered structure, ONE change: Bs stored with 10-float
// per-tx slot stride (t -> (t/8)*10 + t%8). 10*tx mod 32 is distinct for
// tx in [0,16) -> the four B LDS.64 loads are bank-conflict-free (were
// 4-way conflicted at stride 8). 40-byte slots keep 8-B alignment.
// ============================================================
__global__ void __launch_bounds__(256, 2) gemm_kernel(const float* __restrict__ x,
                                                      const float* __restrict__ Min) {
    const int cbase = blockIdx.x * 128;
    const int tbase = blockIdx.y * 128;
    const int b     = blockIdx.z / KSPLIT;
    const int ks    = blockIdx.z % KSPLIT;
    const int kbase = ks * KSEG;

    __shared__ float As[2][8][132];
    __shared__ float Bs[2][8][160];   // 16 tx-slots x 10 floats

    const int tid = threadIdx.x;
    const int a_k = tid >> 5;
    const int a_c = (tid & 31) << 2;
    const int b_t = tid >> 1;                       // t index 0..127
    const int b_k = (tid & 1) << 2;
    const int b_off = (b_t >> 3) * 10 + (b_t & 7);  // strided slot offset
    const int tx = tid & 15;
    const int ty = tid >> 4;

    const float* Ap = Min + (size_t)(kbase + a_k) * D + cbase + a_c;
    const float* Bp = x + ((size_t)b * T + tbase + b_t) * D + kbase + b_k;

    ull acc[8][4];
#pragma unroll
    for (int i = 0; i < 8; i++)
#pragma unroll
        for (int j = 0; j < 4; j++) acc[i][j] = 0ull;

    {
        float4 av = *(const float4*)Ap;
        float4 bv = *(const float4*)Bp;
        *(float4*)&As[0][a_k][a_c] = av;
        Bs[0][b_k + 0][b_off] = bv.x;
        Bs[0][b_k + 1][b_off] = bv.y;
        Bs[0][b_k + 2][b_off] = bv.z;
        Bs[0][b_k + 3][b_off] = bv.w;
    }
    __syncthreads();

#pragma unroll 2
    for (int kt = 0; kt < KSEG / 8; kt++) {
        const int cur = kt & 1;
        float4 av, bv;
        const bool more = (kt + 1 < KSEG / 8);
        if (more) {
            Ap += 8 * D;
            Bp += 8;
            av = *(const float4*)Ap;
            bv = *(const float4*)Bp;
        }
#pragma unroll
        for (int kk = 0; kk < 8; kk++) {
            float4 af0 = *(const float4*)&As[cur][kk][ty * 8];
            float4 af1 = *(const float4*)&As[cur][kk][ty * 8 + 4];
            const float* brow = &Bs[cur][kk][tx * 10];
            ull b20 = *(const ull*)(brow + 0);
            ull b21 = *(const ull*)(brow + 2);
            ull b22 = *(const ull*)(brow + 4);
            ull b23 = *(const ull*)(brow + 6);
            float a[8] = {af0.x, af0.y, af0.z, af0.w, af1.x, af1.y, af1.z, af1.w};
#pragma unroll
            for (int i = 0; i < 8; i++) {
                ull ai = pack2(a[i], a[i]);
                acc[i][0] = ffma2(ai, b20, acc[i][0]);
                acc[i][1] = ffma2(ai, b21, acc[i][1]);
                acc[i][2] = ffma2(ai, b22, acc[i][2]);
                acc[i][3] = ffma2(ai, b23, acc[i][3]);
            }
        }
        if (more) {
            const int nxt = cur ^ 1;
            *(float4*)&As[nxt][a_k][a_c] = av;
            Bs[nxt][b_k + 0][b_off] = bv.x;
            Bs[nxt][b_k + 1][b_off] = bv.y;
            Bs[nxt][b_k + 2][b_off] = bv.z;
            Bs[nxt][b_k + 3][b_off] = bv.w;
            __syncthreads();
        }
    }

    float* outbase = g_xp + (size_t)ks * ROWS * T;
#pragma unroll
    for (int i = 0; i < 8; i++) {
        int row = b * D + cbase + ty * 8 + i;
        float* dst = outbase + (size_t)row * T + tbase + tx * 8;
        float2 p0 = unpack2(acc[i][0]);
        float2 p1 = unpack2(acc[i][1]);
        float2 p2 = unpack2(acc[i][2]);
        float2 p3 = unpack2(acc[i][3]);
        *(float4*)dst       = make_float4(p0.x, p0.y, p1.x, p1.y);
        *(float4*)(dst + 4) = make_float4(p2.x, p2.y, p3.x, p3.y);
    }
}

// ============================================================
// Scan — R7 structure VERBATIM (empirically fastest).
// ============================================================
constexpr int SCAN_WARPS = 4;

__global__ void __launch_bounds__(SCAN_WARPS * 32) scan_kernel(const float* __restrict__ Ain) {
    __shared__ float sx[SCAN_WARPS][32];
    __shared__ float sp[SCAN_WARPS][32 * 33];

    const int warp = threadIdx.x >> 5;
    const int lane = threadIdx.x & 31;
    const int row = blockIdx.x * SCAN_WARPS + warp;  // 0..1535
    const int c = row % D;

    ull A20 = *(const ull*)(Ain + 2 * lane);
    ull A21 = *(const ull*)(Ain + 64 + 2 * lane);
    const float* Wr = g_Wt + (size_t)c * S;
    ull W20 = *(const ull*)(Wr + 2 * lane);
    ull W21 = *(const ull*)(Wr + 64 + 2 * lane);

    const float* x0 = g_xp + (size_t)row * T;
    const float* x1 = x0 + (size_t)ROWS * T;
    const float* x2 = x1 + (size_t)ROWS * T;
    float* yr = g_yp + (size_t)row * T;

    float* sxm = sx[warp];
    float* spm = sp[warp];

    ull h0 = 0ull, h1 = 0ull;

    float xv = x0[lane] + x1[lane] + x2[lane];  // sum K-split partials
    for (int t0 = 0; t0 < T; t0 += 32) {
        sxm[lane] = xv;
        __syncwarp();
        if (t0 + 32 < T) {  // prefetch next block
            int t = t0 + 32 + lane;
            xv = x0[t] + x1[t] + x2[t];
        }
#pragma unroll
        for (int tt = 0; tt < 32; tt++) {
            float xs = sxm[tt];
            ull xx = pack2(xs, xs);
            h0 = ffma2(A20, h0, xx);
            h1 = ffma2(A21, h1, xx);
            ull p = fmul2(h0, W20);
            p = ffma2(h1, W21, p);
            float2 pf = unpack2(p);
            spm[tt * 33 + lane] = pf.x + pf.y;  // conflict-free
        }
        __syncwarp();
        const float* col = spm + lane * 33;
        float a0 = 0.f, a1 = 0.f, a2 = 0.f, a3 = 0.f;
#pragma unroll
        for (int l = 0; l < 32; l += 4) {
            a0 += col[l];
            a1 += col[l + 1];
            a2 += col[l + 2];
            a3 += col[l + 3];
        }
        yr[t0 + lane] = (a0 + a1) + (a2 + a3);
        __syncwarp();
    }
}

// ============================================================
// Transpose (row,t) fp32 -> (b,t,c), output f32 on bf16 grid
// ============================================================
__global__ void transpose_kernel(float* __restrict__ out) {
    __shared__ float tile[32][33];
    const int t0 = blockIdx.x * 32;
    const int c0 = blockIdx.y * 32;
    const int b = blockIdx.z;
    const int tx = threadIdx.x, ty = threadIdx.y;
#pragma unroll
    for (int i = 0; i < 32; i += 8)
        tile[ty + i][tx] = g_yp[(size_t)(b * D + c0 + ty + i) * T + t0 + tx];
    __syncthreads();
#pragma unroll
    for (int i = 0; i < 32; i += 8) {
        float v = tile[tx][ty + i];
        out[(size_t)(b * T + t0 + ty + i) * D + c0 + tx] =
            __bfloat162float(__float2bfloat16(v));
    }
}

// ============================================================
extern "C" void kernel_launch(void* const* d_in, const int* in_sizes, int n_in,
                              void* d_out, int out_size) {
    const float* x = nullptr;
    const float *Min = nullptr, *Mfil = nullptr, *A = nullptr, *BC = nullptr;
    for (int i = 0; i < n_in; i++) {
        switch (in_sizes[i]) {  // all five element counts are distinct
            case B * T * D:     x    = (const float*)d_in[i]; break;  // 1572864
            case D * D:         Min  = (const float*)d_in[i]; break;  // 589824
            case HALF * D:      Mfil = (const float*)d_in[i]; break;  // 18432
            case S:             A    = (const float*)d_in[i]; break;  // 128
            case S * 2 * HALF:  BC   = (const float*)d_in[i]; break;  // 6144
        }
    }

    prep_w<<<dim3(S, 3), 256>>>(BC, Mfil);
    gemm_kernel<<<dim3(D / 128, T / 128, B * KSPLIT), 256>>>(x, Min);
    scan_kernel<<<ROWS / SCAN_WARPS, SCAN_WARPS * 32>>>(A);
    transpose_kernel<<<dim3(T / 32, D / 32, B), dim3(32, 8)>>>((float*)d_out);
}

// round 15
// speedup vs baseline: 2.8571x; 1.1618x over previous
#include <cuda_runtime.h>
#include <cuda_bf16.h>
#include <cstdint>

typedef unsigned long long ull;

#define DI static __device__ __forceinline__

// ---- packed f32x2 helpers (sm_100a) ----
DI ull ffma2(ull a, ull b, ull c) {
    ull d;
    asm("fma.rn.f32x2 %0, %1, %2, %3;" : "=l"(d) : "l"(a), "l"(b), "l"(c));
    return d;
}
DI ull fmul2(ull a, ull b) {
    ull d;
    asm("mul.rn.f32x2 %0, %1, %2;" : "=l"(d) : "l"(a), "l"(b));
    return d;
}
DI ull pack2(float lo, float hi) {
    ull d;
    asm("mov.b64 %0, {%1, %2};" : "=l"(d) : "f"(lo), "f"(hi));
    return d;
}
DI float2 unpack2(ull v) {
    float2 r;
    asm("mov.b64 {%0, %1}, %2;" : "=f"(r.x), "=f"(r.y) : "l"(v));
    return r;
}

// ---- mma.sync / ldmatrix helpers (portable sm_80+ path) ----
DI uint32_t smem_u32(const void* p) {
    uint32_t a;
    asm("{ .reg .u64 t; cvta.to.shared.u64 t, %1; cvt.u32.u64 %0, t; }" : "=r"(a) : "l"(p));
    return a;
}
DI void ldm4(uint32_t* r, uint32_t addr) {
    asm volatile("ldmatrix.sync.aligned.m8n8.x4.shared.b16 {%0,%1,%2,%3}, [%4];"
                 : "=r"(r[0]), "=r"(r[1]), "=r"(r[2]), "=r"(r[3]) : "r"(addr));
}
DI void mma16816(float* d, const uint32_t* a, const uint32_t* b) {
    asm volatile(
        "mma.sync.aligned.m16n8k16.row.col.f32.bf16.bf16.f32 "
        "{%0,%1,%2,%3}, {%4,%5,%6,%7}, {%8,%9}, {%0,%1,%2,%3};"
        : "+f"(d[0]), "+f"(d[1]), "+f"(d[2]), "+f"(d[3])
        : "r"(a[0]), "r"(a[1]), "r"(a[2]), "r"(a[3]), "r"(b[0]), "r"(b[1]));
}

constexpr int B = 2, T = 1024, D = 768, S = 128, HALF = 24;
constexpr int ROWS = B * D;  // 1536
constexpr int KSPLIT = 2, KHALF = 384;   // GEMM K split
constexpr int PITCH = 40;                // bf16 smem row pitch (conflict-free ldmatrix)
constexpr int NCHUNK = KHALF / 32;       // 12

// ---- device scratch (static: no allocation) ----
__device__ float g_Wt[D * S];
__device__ float g_xp[KSPLIT * ROWS * T];   // K-split partials, (row,t)
__device__ float g_yp[ROWS * T];
__device__ __nv_bfloat16 g_xhi[B * T * D];
__device__ __nv_bfloat16 g_xlo[B * T * D];
__device__ __nv_bfloat16 g_mhiT[D * D];     // M^T hi, [c][k]
__device__ __nv_bfloat16 g_mloT[D * D];     // M^T lo, [c][k]

// ============================================================
// prep_w (unchanged)
// ============================================================
__global__ void prep_w(const float* __restrict__ BC, const float* __restrict__ Mfil) {
    int s = blockIdx.x;
    int c = blockIdx.y * 256 + threadIdx.x;
    float acc = 0.f;
#pragma unroll
    for (int k = 0; k < HALF; k++) {
        float bsum = BC[s * 2 * HALF + k] + BC[s * 2 * HALF + HALF + k];
        acc = fmaf(bsum, Mfil[k * D + c], acc);
    }
    g_Wt[(size_t)c * S + s] = acc;
}

// ============================================================
// x -> (xhi, xlo) bf16 split
// ============================================================
__global__ void prep_split_x(const float* __restrict__ x) {
    int i = (blockIdx.x * blockDim.x + threadIdx.x) * 2;
    float v0 = x[i], v1 = x[i + 1];
    __nv_bfloat16 h0 = __float2bfloat16(v0), h1 = __float2bfloat16(v1);
    __nv_bfloat16 l0 = __float2bfloat16(v0 - __bfloat162float(h0));
    __nv_bfloat16 l1 = __float2bfloat16(v1 - __bfloat162float(h1));
    *(__nv_bfloat162*)(g_xhi + i) = __nv_bfloat162(h0, h1);
    *(__nv_bfloat162*)(g_xlo + i) = __nv_bfloat162(l0, l1);
}

// ============================================================
// M[k][c] -> transposed bf16 split MhiT/MloT [c][k]
// ============================================================
__global__ void prep_split_mT(const float* __restrict__ Min) {
    __shared__ float tile[32][33];
    const int kb = blockIdx.x * 32, cb = blockIdx.y * 32;
    const int tx = threadIdx.x, ty = threadIdx.y;
#pragma unroll
    for (int i = 0; i < 32; i += 8)
        tile[ty + i][tx] = Min[(size_t)(kb + ty + i) * D + cb + tx];
    __syncthreads();
#pragma unroll
    for (int i = 0; i < 32; i += 8) {
        float v = tile[tx][ty + i];
        __nv_bfloat16 h = __float2bfloat16(v);
        __nv_bfloat16 l = __float2bfloat16(v - __bfloat162float(h));
        size_t o = (size_t)(cb + ty + i) * D + kb + tx;
        g_mhiT[o] = h;
        g_mloT[o] = l;
    }
}

// ============================================================
// Tensor-core GEMM via mma.sync m16n8k16 bf16, 3-pass split
// (hi*hi + hi*lo + lo*hi). CTA 128c x 64t, warps 4(c) x 2(t),
// warp tile 32x32. K chunk 32, register-prefetched. K split 2.
// ============================================================
__global__ void __launch_bounds__(256, 2) gemm_mma() {
    __shared__ __nv_bfloat16 Ah[128 * PITCH], Al[128 * PITCH];
    __shared__ __nv_bfloat16 Bh[64 * PITCH], Bl[64 * PITCH];

    const int tid = threadIdx.x;
    const int wid = tid >> 5;
    const int lane = tid & 31;
    const int wc = wid >> 1;      // 0..3 (c)
    const int wt = wid & 1;       // 0..1 (t)
    const int cbase = blockIdx.x * 128;
    const int tbase = blockIdx.y * 64;
    const int bb = blockIdx.z >> 1;
    const int ks = blockIdx.z & 1;
    const int kbase = ks * KHALF;

    // global-load assignments (uint4 = 8 bf16)
    const int a_row = tid >> 2, a_g = tid & 3;         // +128 rows for second half
    const int b_row = tid >> 2, b_g = tid & 3;         // b_row < 64

    float acc[2][4][4];
#pragma unroll
    for (int i = 0; i < 2; i++)
#pragma unroll
        for (int j = 0; j < 4; j++)
#pragma unroll
            for (int q = 0; q < 4; q++) acc[i][j][q] = 0.f;

    uint4 rAh0, rAh1, rAl0, rAl1, rBh, rBl;
    {
        const size_t a0 = (size_t)(cbase + a_row) * D + kbase + a_g * 8;
        const size_t a1 = (size_t)(cbase + a_row + 64) * D + kbase + a_g * 8;
        const size_t bo = (size_t)(bb * T + tbase + b_row) * D + kbase + b_g * 8;
        rAh0 = *(const uint4*)(g_mhiT + a0);
        rAh1 = *(const uint4*)(g_mhiT + a1);
        rAl0 = *(const uint4*)(g_mloT + a0);
        rAl1 = *(const uint4*)(g_mloT + a1);
        rBh  = *(const uint4*)(g_xhi + bo);
        rBl  = *(const uint4*)(g_xlo + bo);
    }

    for (int ch = 0; ch < NCHUNK; ch++) {
        __syncthreads();
        *(uint4*)(Ah + a_row * PITCH + a_g * 8)        = rAh0;
        *(uint4*)(Ah + (a_row + 64) * PITCH + a_g * 8) = rAh1;
        *(uint4*)(Al + a_row * PITCH + a_g * 8)        = rAl0;
        *(uint4*)(Al + (a_row + 64) * PITCH + a_g * 8) = rAl1;
        *(uint4*)(Bh + b_row * PITCH + b_g * 8)        = rBh;
        *(uint4*)(Bl + b_row * PITCH + b_g * 8)        = rBl;
        __syncthreads();
        if (ch + 1 < NCHUNK) {
            const int k0 = kbase + (ch + 1) * 32;
            const size_t a0 = (size_t)(cbase + a_row) * D + k0 + a_g * 8;
            const size_t a1 = (size_t)(cbase + a_row + 64) * D + k0 + a_g * 8;
            const size_t bo = (size_t)(bb * T + tbase + b_row) * D + k0 + b_g * 8;
            rAh0 = *(const uint4*)(g_mhiT + a0);
            rAh1 = *(const uint4*)(g_mhiT + a1);
            rAl0 = *(const uint4*)(g_mloT + a0);
            rAl1 = *(const uint4*)(g_mloT + a1);
            rBh  = *(const uint4*)(g_xhi + bo);
            rBl  = *(const uint4*)(g_xlo + bo);
        }
#pragma unroll
        for (int ks16 = 0; ks16 < 2; ks16++) {
            uint32_t afh[2][4], afl[2][4], bfh[4][2], bfl[4][2];
            // A fragments: lanes 0-15 rows 0-15 @k0; 16-31 rows 0-15 @k8
            const int ar = (lane & 15);
            const int acol = ks16 * 16 + (lane >> 4) * 8;
#pragma unroll
            for (int mt = 0; mt < 2; mt++) {
                int row = wc * 32 + mt * 16 + ar;
                ldm4(afh[mt], smem_u32(Ah + row * PITCH + acol));
                ldm4(afl[mt], smem_u32(Al + row * PITCH + acol));
            }
            // B fragments: lanes {0-7,8-15,16-23,24-31} -> (n0-7@k0, n0-7@k8,
            // n8-15@k0, n8-15@k8); x4 covers two n8 tiles
            const int bn = (lane & 7) | ((lane & 16) >> 1);
            const int bcol = ks16 * 16 + ((lane >> 3) & 1) * 8;
#pragma unroll
            for (int pr = 0; pr < 2; pr++) {
                int row = wt * 32 + pr * 16 + bn;
                uint32_t r[4];
                ldm4(r, smem_u32(Bh + row * PITCH + bcol));
                bfh[2 * pr][0] = r[0]; bfh[2 * pr][1] = r[1];
                bfh[2 * pr + 1][0] = r[2]; bfh[2 * pr + 1][1] = r[3];
                ldm4(r, smem_u32(Bl + row * PITCH + bcol));
                bfl[2 * pr][0] = r[0]; bfl[2 * pr][1] = r[1];
                bfl[2 * pr + 1][0] = r[2]; bfl[2 * pr + 1][1] = r[3];
            }
#pragma unroll
            for (int mt = 0; mt < 2; mt++)
#pragma unroll
                for (int nt = 0; nt < 4; nt++) {
                    mma16816(acc[mt][nt], afh[mt], bfh[nt]);
                    mma16816(acc[mt][nt], afh[mt], bfl[nt]);
                    mma16816(acc[mt][nt], afl[mt], bfh[nt]);
                }
        }
    }

    // epilogue: thread holds (c = base + l/4 (+8), t = nt*8 + 2*(l%4) + {0,1})
    float* outp = g_xp + (size_t)ks * ROWS * T;
#pragma unroll
    for (int mt = 0; mt < 2; mt++) {
        const int cl = wc * 32 + mt * 16 + (lane >> 2);
#pragma unroll
        for (int nt = 0; nt < 4; nt++) {
            const int tl = wt * 32 + nt * 8 + 2 * (lane & 3);
            size_t o0 = (size_t)(bb * D + cbase + cl) * T + tbase + tl;
            *(float2*)(outp + o0) = make_float2(acc[mt][nt][0], acc[mt][nt][1]);
            *(float2*)(outp + o0 + 8 * (size_t)T) = make_float2(acc[mt][nt][2], acc[mt][nt][3]);
        }
    }
}

// ============================================================
// Scan — R7 structure verbatim, 2 K-split partials
// ============================================================
constexpr int SCAN_WARPS = 4;

__global__ void __launch_bounds__(SCAN_WARPS * 32) scan_kernel(const float* __restrict__ Ain) {
    __shared__ float sx[SCAN_WARPS][32];
    __shared__ float sp[SCAN_WARPS][32 * 33];

    const int warp = threadIdx.x >> 5;
    const int lane = threadIdx.x & 31;
    const int row = blockIdx.x * SCAN_WARPS + warp;
    const int c = row % D;

    ull A20 = *(const ull*)(Ain + 2 * lane);
    ull A21 = *(const ull*)(Ain + 64 + 2 * lane);
    const float* Wr = g_Wt + (size_t)c * S;
    ull W20 = *(const ull*)(Wr + 2 * lane);
    ull W21 = *(const ull*)(Wr + 64 + 2 * lane);

    const float* x0 = g_xp + (size_t)row * T;
    const float* x1 = x0 + (size_t)ROWS * T;
    float* yr = g_yp + (size_t)row * T;

    float* sxm = sx[warp];
    float* spm = sp[warp];

    ull h0 = 0ull, h1 = 0ull;

    float xv = x0[lane] + x1[lane];
    for (int t0 = 0; t0 < T; t0 += 32) {
        sxm[lane] = xv;
        __syncwarp();
        if (t0 + 32 < T) {
            int t = t0 + 32 + lane;
            xv = x0[t] + x1[t];
        }
#pragma unroll
        for (int tt = 0; tt < 32; tt++) {
            float xs = sxm[tt];
            ull xx = pack2(xs, xs);
            h0 = ffma2(A20, h0, xx);
            h1 = ffma2(A21, h1, xx);
            ull p = fmul2(h0, W20);
            p = ffma2(h1, W21, p);
            float2 pf = unpack2(p);
            spm[tt * 33 + lane] = pf.x + pf.y;
        }
        __syncwarp();
        const float* col = spm + lane * 33;
        float a0 = 0.f, a1 = 0.f, a2 = 0.f, a3 = 0.f;
#pragma unroll
        for (int l = 0; l < 32; l += 4) {
            a0 += col[l];
            a1 += col[l + 1];
            a2 += col[l + 2];
            a3 += col[l + 3];
        }
        yr[t0 + lane] = (a0 + a1) + (a2 + a3);
        __syncwarp();
    }
}

// ============================================================
// Transpose (row,t) fp32 -> (b,t,c), output f32 on bf16 grid
// ============================================================
__global__ void transpose_kernel(float* __restrict__ out) {
    __shared__ float tile[32][33];
    const int t0 = blockIdx.x * 32;
    const int c0 = blockIdx.y * 32;
    const int b = blockIdx.z;
    const int tx = threadIdx.x, ty = threadIdx.y;
#pragma unroll
    for (int i = 0; i < 32; i += 8)
        tile[ty + i][tx] = g_yp[(size_t)(b * D + c0 + ty + i) * T + t0 + tx];
    __syncthreads();
#pragma unroll
    for (int i = 0; i < 32; i += 8) {
        float v = tile[tx][ty + i];
        out[(size_t)(b * T + t0 + ty + i) * D + c0 + tx] =
            __bfloat162float(__float2bfloat16(v));
    }
}

// ============================================================
extern "C" void kernel_launch(void* const* d_in, const int* in_sizes, int n_in,
                              void* d_out, int out_size) {
    const float* x = nullptr;
    const float *Min = nullptr, *Mfil = nullptr, *A = nullptr, *BC = nullptr;
    for (int i = 0; i < n_in; i++) {
        switch (in_sizes[i]) {  // all five element counts are distinct
            case B * T * D:     x    = (const float*)d_in[i]; break;
            case D * D:         Min  = (const float*)d_in[i]; break;
            case HALF * D:      Mfil = (const float*)d_in[i]; break;
            case S:             A    = (const float*)d_in[i]; break;
            case S * 2 * HALF:  BC   = (const float*)d_in[i]; break;
        }
    }

    prep_w<<<dim3(S, 3), 256>>>(BC, Mfil);
    prep_split_x<<<(B * T * D / 2) / 256, 256>>>(x);
    prep_split_mT<<<dim3(D / 32, D / 32), dim3(32, 8)>>>(Min);
    gemm_mma<<<dim3(D / 128, T / 64, B * KSPLIT), 256>>>();
    scan_kernel<<<ROWS / SCAN_WARPS, SCAN_WARPS * 32>>>(A);
    transpose_kernel<<<dim3(T / 32, D / 32, B), dim3(32, 8)>>>((float*)d_out);
}

// round 16
// speedup vs baseline: 2.8602x; 1.0011x over previous
#include <cuda_runtime.h>
#include <cuda_bf16.h>
#include <cstdint>

typedef unsigned long long ull;

#define DI static __device__ __forceinline__

// ---- packed f32x2 helpers (sm_100a) ----
DI ull ffma2(ull a, ull b, ull c) {
    ull d;
    asm("fma.rn.f32x2 %0, %1, %2, %3;" : "=l"(d) : "l"(a), "l"(b), "l"(c));
    return d;
}
DI ull fmul2(ull a, ull b) {
    ull d;
    asm("mul.rn.f32x2 %0, %1, %2;" : "=l"(d) : "l"(a), "l"(b));
    return d;
}
DI ull pack2(float lo, float hi) {
    ull d;
    asm("mov.b64 %0, {%1, %2};" : "=l"(d) : "f"(lo), "f"(hi));
    return d;
}
DI float2 unpack2(ull v) {
    float2 r;
    asm("mov.b64 {%0, %1}, %2;" : "=f"(r.x), "=f"(r.y) : "l"(v));
    return r;
}

// ---- mma.sync / ldmatrix / cp.async helpers (portable sm_80+ path) ----
DI uint32_t smem_u32(const void* p) {
    uint32_t a;
    asm("{ .reg .u64 t; cvta.to.shared.u64 t, %1; cvt.u32.u64 %0, t; }" : "=r"(a) : "l"(p));
    return a;
}
DI void ldm4(uint32_t* r, uint32_t addr) {
    asm volatile("ldmatrix.sync.aligned.m8n8.x4.shared.b16 {%0,%1,%2,%3}, [%4];"
                 : "=r"(r[0]), "=r"(r[1]), "=r"(r[2]), "=r"(r[3]) : "r"(addr));
}
DI void mma16816(float* d, const uint32_t* a, const uint32_t* b) {
    asm volatile(
        "mma.sync.aligned.m16n8k16.row.col.f32.bf16.bf16.f32 "
        "{%0,%1,%2,%3}, {%4,%5,%6,%7}, {%8,%9}, {%0,%1,%2,%3};"
        : "+f"(d[0]), "+f"(d[1]), "+f"(d[2]), "+f"(d[3])
        : "r"(a[0]), "r"(a[1]), "r"(a[2]), "r"(a[3]), "r"(b[0]), "r"(b[1]));
}
DI void cp16(uint32_t smem_dst, const void* gsrc) {
    asm volatile("cp.async.cg.shared.global [%0], [%1], 16;"
                 :: "r"(smem_dst), "l"(gsrc) : "memory");
}
DI void cp_commit() { asm volatile("cp.async.commit_group;" ::: "memory"); }
template <int N> DI void cp_wait() {
    asm volatile("cp.async.wait_group %0;" :: "n"(N) : "memory");
}

constexpr int B = 2, T = 1024, D = 768, S = 128, HALF = 24;
constexpr int ROWS = B * D;  // 1536
constexpr int KSPLIT = 2, KHALF = 384;   // GEMM K split
constexpr int PITCH = 40;                // bf16 smem row pitch (conflict-free ldmatrix)
constexpr int NCHUNK = KHALF / 32;       // 12

// smem stage layout (bytes)
constexpr int OFF_AH = 0;
constexpr int OFF_AL = 128 * PITCH * 2;            // 10240
constexpr int OFF_BH = OFF_AL + 128 * PITCH * 2;   // 20480
constexpr int OFF_BL = OFF_BH + 64 * PITCH * 2;    // 25600
constexpr int STAGE  = OFF_BL + 64 * PITCH * 2;    // 30720
constexpr int GEMM_SMEM = 2 * STAGE;               // 61440

// ---- device scratch (static: no allocation) ----
__device__ float g_Wt[D * S];
__device__ float g_xp[KSPLIT * ROWS * T];   // K-split partials, (row,t)
__device__ float g_yp[ROWS * T];
__device__ __nv_bfloat16 g_xhi[B * T * D];
__device__ __nv_bfloat16 g_xlo[B * T * D];
__device__ __nv_bfloat16 g_mhiT[D * D];     // M^T hi, [c][k]
__device__ __nv_bfloat16 g_mloT[D * D];     // M^T lo, [c][k]

// ============================================================
// prep_w (unchanged)
// ============================================================
__global__ void prep_w(const float* __restrict__ BC, const float* __restrict__ Mfil) {
    int s = blockIdx.x;
    int c = blockIdx.y * 256 + threadIdx.x;
    float acc = 0.f;
#pragma unroll
    for (int k = 0; k < HALF; k++) {
        float bsum = BC[s * 2 * HALF + k] + BC[s * 2 * HALF + HALF + k];
        acc = fmaf(bsum, Mfil[k * D + c], acc);
    }
    g_Wt[(size_t)c * S + s] = acc;
}

// ============================================================
// x -> (xhi, xlo) bf16 split
// ============================================================
__global__ void prep_split_x(const float* __restrict__ x) {
    int i = (blockIdx.x * blockDim.x + threadIdx.x) * 2;
    float v0 = x[i], v1 = x[i + 1];
    __nv_bfloat16 h0 = __float2bfloat16(v0), h1 = __float2bfloat16(v1);
    __nv_bfloat16 l0 = __float2bfloat16(v0 - __bfloat162float(h0));
    __nv_bfloat16 l1 = __float2bfloat16(v1 - __bfloat162float(h1));
    *(__nv_bfloat162*)(g_xhi + i) = __nv_bfloat162(h0, h1);
    *(__nv_bfloat162*)(g_xlo + i) = __nv_bfloat162(l0, l1);
}

// ============================================================
// M[k][c] -> transposed bf16 split MhiT/MloT [c][k]
// ============================================================
__global__ void prep_split_mT(const float* __restrict__ Min) {
    __shared__ float tile[32][33];
    const int kb = blockIdx.x * 32, cb = blockIdx.y * 32;
    const int tx = threadIdx.x, ty = threadIdx.y;
#pragma unroll
    for (int i = 0; i < 32; i += 8)
        tile[ty + i][tx] = Min[(size_t)(kb + ty + i) * D + cb + tx];
    __syncthreads();
#pragma unroll
    for (int i = 0; i < 32; i += 8) {
        float v = tile[tx][ty + i];
        __nv_bfloat16 h = __float2bfloat16(v);
        __nv_bfloat16 l = __float2bfloat16(v - __bfloat162float(h));
        size_t o = (size_t)(cb + ty + i) * D + kb + tx;
        g_mhiT[o] = h;
        g_mloT[o] = l;
    }
}

// ============================================================
// Tensor-core GEMM via mma.sync m16n8k16 bf16, 3-pass split
// (hi*hi + hi*lo + lo*hi). CTA 128c x 64t, warps 4(c) x 2(t),
// warp tile 32x32. K chunk 32. cp.async double-buffered smem.
// ============================================================
__global__ void __launch_bounds__(256, 2) gemm_mma() {
    extern __shared__ char smp[];

    const int tid = threadIdx.x;
    const int wid = tid >> 5;
    const int lane = tid & 31;
    const int wc = wid >> 1;      // 0..3 (c)
    const int wt = wid & 1;       // 0..1 (t)
    const int cbase = blockIdx.x * 128;
    const int tbase = blockIdx.y * 64;
    const int bb = blockIdx.z >> 1;
    const int ks = blockIdx.z & 1;
    const int kbase = ks * KHALF;

    // global-load assignments (16 B = 8 bf16 per cp.async)
    const int a_row = tid >> 2, a_g = tid & 3;
    const int b_row = tid >> 2, b_g = tid & 3;
    const uint32_t sb = smem_u32(smp);
    const uint32_t dA0 = sb + OFF_AH + (a_row * PITCH + a_g * 8) * 2;
    const uint32_t dA1 = sb + OFF_AH + ((a_row + 64) * PITCH + a_g * 8) * 2;
    const uint32_t dL0 = sb + OFF_AL + (a_row * PITCH + a_g * 8) * 2;
    const uint32_t dL1 = sb + OFF_AL + ((a_row + 64) * PITCH + a_g * 8) * 2;
    const uint32_t dBH = sb + OFF_BH + (b_row * PITCH + b_g * 8) * 2;
    const uint32_t dBL = sb + OFF_BL + (b_row * PITCH + b_g * 8) * 2;

    float acc[2][4][4];
#pragma unroll
    for (int i = 0; i < 2; i++)
#pragma unroll
        for (int j = 0; j < 4; j++)
#pragma unroll
            for (int q = 0; q < 4; q++) acc[i][j][q] = 0.f;

    auto issue_loads = [&](int ch, int stg) {
        const int k0 = kbase + ch * 32;
        const size_t a0 = (size_t)(cbase + a_row) * D + k0 + a_g * 8;
        const size_t a1 = (size_t)(cbase + a_row + 64) * D + k0 + a_g * 8;
        const size_t bo = (size_t)(bb * T + tbase + b_row) * D + k0 + b_g * 8;
        const uint32_t so = stg * STAGE;
        cp16(dA0 + so, g_mhiT + a0);
        cp16(dA1 + so, g_mhiT + a1);
        cp16(dL0 + so, g_mloT + a0);
        cp16(dL1 + so, g_mloT + a1);
        cp16(dBH + so, g_xhi + bo);
        cp16(dBL + so, g_xlo + bo);
        cp_commit();
    };

    issue_loads(0, 0);

    for (int ch = 0; ch < NCHUNK; ch++) {
        const int stg = ch & 1;
        if (ch + 1 < NCHUNK) {
            issue_loads(ch + 1, stg ^ 1);
            cp_wait<1>();   // stage ch complete; ch+1 still in flight
        } else {
            cp_wait<0>();
        }
        __syncthreads();   // publish stage ch to all threads

        const __nv_bfloat16* Ah = (const __nv_bfloat16*)(smp + stg * STAGE + OFF_AH);
        const __nv_bfloat16* Al = (const __nv_bfloat16*)(smp + stg * STAGE + OFF_AL);
        const __nv_bfloat16* Bh = (const __nv_bfloat16*)(smp + stg * STAGE + OFF_BH);
        const __nv_bfloat16* Bl = (const __nv_bfloat16*)(smp + stg * STAGE + OFF_BL);

#pragma unroll
        for (int ks16 = 0; ks16 < 2; ks16++) {
            uint32_t afh[2][4], afl[2][4], bfh[4][2], bfl[4][2];
            const int ar = (lane & 15);
            const int acol = ks16 * 16 + (lane >> 4) * 8;
#pragma unroll
            for (int mt = 0; mt < 2; mt++) {
                int row = wc * 32 + mt * 16 + ar;
                ldm4(afh[mt], smem_u32(Ah + row * PITCH + acol));
                ldm4(afl[mt], smem_u32(Al + row * PITCH + acol));
            }
            const int bn = (lane & 7) | ((lane & 16) >> 1);
            const int bcol = ks16 * 16 + ((lane >> 3) & 1) * 8;
#pragma unroll
            for (int pr = 0; pr < 2; pr++) {
                int row = wt * 32 + pr * 16 + bn;
                uint32_t r[4];
                ldm4(r, smem_u32(Bh + row * PITCH + bcol));
                bfh[2 * pr][0] = r[0]; bfh[2 * pr][1] = r[1];
                bfh[2 * pr + 1][0] = r[2]; bfh[2 * pr + 1][1] = r[3];
                ldm4(r, smem_u32(Bl + row * PITCH + bcol));
                bfl[2 * pr][0] = r[0]; bfl[2 * pr][1] = r[1];
                bfl[2 * pr + 1][0] = r[2]; bfl[2 * pr + 1][1] = r[3];
            }
#pragma unroll
            for (int mt = 0; mt < 2; mt++)
#pragma unroll
                for (int nt = 0; nt < 4; nt++) {
                    mma16816(acc[mt][nt], afh[mt], bfh[nt]);
                    mma16816(acc[mt][nt], afh[mt], bfl[nt]);
                    mma16816(acc[mt][nt], afl[mt], bfh[nt]);
                }
        }
        __syncthreads();   // stage ch free before iter ch+1 overwrites it (ch+2 load)
    }

    // epilogue: thread holds (c = base + l/4 (+8), t = nt*8 + 2*(l%4) + {0,1})
    float* outp = g_xp + (size_t)ks * ROWS * T;
#pragma unroll
    for (int mt = 0; mt < 2; mt++) {
        const int cl = wc * 32 + mt * 16 + (lane >> 2);
#pragma unroll
        for (int nt = 0; nt < 4; nt++) {
            const int tl = wt * 32 + nt * 8 + 2 * (lane & 3);
            size_t o0 = (size_t)(bb * D + cbase + cl) * T + tbase + tl;
            *(float2*)(outp + o0) = make_float2(acc[mt][nt][0], acc[mt][nt][1]);
            *(float2*)(outp + o0 + 8 * (size_t)T) = make_float2(acc[mt][nt][2], acc[mt][nt][3]);
        }
    }
}

// ============================================================
// Scan — R7 structure verbatim, 2 K-split partials
// ============================================================
constexpr int SCAN_WARPS = 4;

__global__ void __launch_bounds__(SCAN_WARPS * 32) scan_kernel(const float* __restrict__ Ain) {
    __shared__ float sx[SCAN_WARPS][32];
    __shared__ float sp[SCAN_WARPS][32 * 33];

    const int warp = threadIdx.x >> 5;
    const int lane = threadIdx.x & 31;
    const int row = blockIdx.x * SCAN_WARPS + warp;
    const int c = row % D;

    ull A20 = *(const ull*)(Ain + 2 * lane);
    ull A21 = *(const ull*)(Ain + 64 + 2 * lane);
    const float* Wr = g_Wt + (size_t)c * S;
    ull W20 = *(const ull*)(Wr + 2 * lane);
    ull W21 = *(const ull*)(Wr + 64 + 2 * lane);

    const float* x0 = g_xp + (size_t)row * T;
    const float* x1 = x0 + (size_t)ROWS * T;
    float* yr = g_yp + (size_t)row * T;

    float* sxm = sx[warp];
    float* spm = sp[warp];

    ull h0 = 0ull, h1 = 0ull;

    float xv = x0[lane] + x1[lane];
    for (int t0 = 0; t0 < T; t0 += 32) {
        sxm[lane] = xv;
        __syncwarp();
        if (t0 + 32 < T) {
            int t = t0 + 32 + lane;
            xv = x0[t] + x1[t];
        }
#pragma unroll
        for (int tt = 0; tt < 32; tt++) {
            float xs = sxm[tt];
            ull xx = pack2(xs, xs);
            h0 = ffma2(A20, h0, xx);
            h1 = ffma2(A21, h1, xx);
            ull p = fmul2(h0, W20);
            p = ffma2(h1, W21, p);
            float2 pf = unpack2(p);
            spm[tt * 33 + lane] = pf.x + pf.y;
        }
        __syncwarp();
        const float* col = spm + lane * 33;
        float a0 = 0.f, a1 = 0.f, a2 = 0.f, a3 = 0.f;
#pragma unroll
        for (int l = 0; l < 32; l += 4) {
            a0 += col[l];
            a1 += col[l + 1];
            a2 += col[l + 2];
            a3 += col[l + 3];
        }
        yr[t0 + lane] = (a0 + a1) + (a2 + a3);
        __syncwarp();
    }
}

// ============================================================
// Transpose (row,t) fp32 -> (b,t,c), output f32 on bf16 grid
// ============================================================
__global__ void transpose_kernel(float* __restrict__ out) {
    __shared__ float tile[32][33];
    const int t0 = blockIdx.x * 32;
    const int c0 = blockIdx.y * 32;
    const int b = blockIdx.z;
    const int tx = threadIdx.x, ty = threadIdx.y;
#pragma unroll
    for (int i = 0; i < 32; i += 8)
        tile[ty + i][tx] = g_yp[(size_t)(b * D + c0 + ty + i) * T + t0 + tx];
    __syncthreads();
#pragma unroll
    for (int i = 0; i < 32; i += 8) {
        float v = tile[tx][ty + i];
        out[(size_t)(b * T + t0 + ty + i) * D + c0 + tx] =
            __bfloat162float(__float2bfloat16(v));
    }
}

// ============================================================
extern "C" void kernel_launch(void* const* d_in, const int* in_sizes, int n_in,
                              void* d_out, int out_size) {
    const float* x = nullptr;
    const float *Min = nullptr, *Mfil = nullptr, *A = nullptr, *BC = nullptr;
    for (int i = 0; i < n_in; i++) {
        switch (in_sizes[i]) {  // all five element counts are distinct
            case B * T * D:     x    = (const float*)d_in[i]; break;
            case D * D:         Min  = (const float*)d_in[i]; break;
            case HALF * D:      Mfil = (const float*)d_in[i]; break;
            case S:             A    = (const float*)d_in[i]; break;
            case S * 2 * HALF:  BC   = (const float*)d_in[i]; break;
        }
    }

    cudaFuncSetAttribute(gemm_mma, cudaFuncAttributeMaxDynamicSharedMemorySize, GEMM_SMEM);

    prep_w<<<dim3(S, 3), 256>>>(BC, Mfil);
    prep_split_x<<<(B * T * D / 2) / 256, 256>>>(x);
    prep_split_mT<<<dim3(D / 32, D / 32), dim3(32, 8)>>>(Min);
    gemm_mma<<<dim3(D / 128, T / 64, B * KSPLIT), 256, GEMM_SMEM>>>();
    scan_kernel<<<ROWS / SCAN_WARPS, SCAN_WARPS * 32>>>(A);
    transpose_kernel<<<dim3(T / 32, D / 32, B), dim3(32, 8)>>>((float*)d_out);
}

// round 17
// speedup vs baseline: 2.9304x; 1.0246x over previous
#include <cuda_runtime.h>
#include <cuda_bf16.h>
#include <cstdint>

typedef unsigned long long ull;

#define DI static __device__ __forceinline__

// ---- packed f32x2 helpers (sm_100a) ----
DI ull ffma2(ull a, ull b, ull c) {
    ull d;
    asm("fma.rn.f32x2 %0, %1, %2, %3;" : "=l"(d) : "l"(a), "l"(b), "l"(c));
    return d;
}
DI ull fmul2(ull a, ull b) {
    ull d;
    asm("mul.rn.f32x2 %0, %1, %2;" : "=l"(d) : "l"(a), "l"(b));
    return d;
}
DI ull pack2(float lo, float hi) {
    ull d;
    asm("mov.b64 %0, {%1, %2};" : "=l"(d) : "f"(lo), "f"(hi));
    return d;
}
DI float2 unpack2(ull v) {
    float2 r;
    asm("mov.b64 {%0, %1}, %2;" : "=f"(r.x), "=f"(r.y) : "l"(v));
    return r;
}

// ---- mma.sync / ldmatrix / cp.async helpers (portable sm_80+ path) ----
DI uint32_t smem_u32(const void* p) {
    uint32_t a;
    asm("{ .reg .u64 t; cvta.to.shared.u64 t, %1; cvt.u32.u64 %0, t; }" : "=r"(a) : "l"(p));
    return a;
}
DI void ldm4(uint32_t* r, uint32_t addr) {
    asm volatile("ldmatrix.sync.aligned.m8n8.x4.shared.b16 {%0,%1,%2,%3}, [%4];"
                 : "=r"(r[0]), "=r"(r[1]), "=r"(r[2]), "=r"(r[3]) : "r"(addr));
}
DI void mma16816(float* d, const uint32_t* a, const uint32_t* b) {
    asm volatile(
        "mma.sync.aligned.m16n8k16.row.col.f32.bf16.bf16.f32 "
        "{%0,%1,%2,%3}, {%4,%5,%6,%7}, {%8,%9}, {%0,%1,%2,%3};"
        : "+f"(d[0]), "+f"(d[1]), "+f"(d[2]), "+f"(d[3])
        : "r"(a[0]), "r"(a[1]), "r"(a[2]), "r"(a[3]), "r"(b[0]), "r"(b[1]));
}
DI void cp16(uint32_t smem_dst, const void* gsrc) {
    asm volatile("cp.async.cg.shared.global [%0], [%1], 16;"
                 :: "r"(smem_dst), "l"(gsrc) : "memory");
}
DI void cp_commit() { asm volatile("cp.async.commit_group;" ::: "memory"); }
template <int N> DI void cp_wait() {
    asm volatile("cp.async.wait_group %0;" :: "n"(N) : "memory");
}

constexpr int B = 2, T = 1024, D = 768, S = 128, HALF = 24;
constexpr int ROWS = B * D;  // 1536
constexpr int KSPLIT = 2, KHALF = 384;   // GEMM K split
constexpr int PITCH = 40;                // bf16 smem row pitch (conflict-free ldmatrix)
constexpr int NCHUNK = KHALF / 32;       // 12
constexpr int NSTAGE = 3;

// smem stage layout (bytes)
constexpr int OFF_AH = 0;
constexpr int OFF_AL = 128 * PITCH * 2;            // 10240
constexpr int OFF_BH = OFF_AL + 128 * PITCH * 2;   // 20480
constexpr int OFF_BL = OFF_BH + 64 * PITCH * 2;    // 25600
constexpr int STAGE  = OFF_BL + 64 * PITCH * 2;    // 30720
constexpr int GEMM_SMEM = NSTAGE * STAGE;          // 92160

// ---- device scratch (static: no allocation) ----
__device__ float g_Wt[D * S];
__device__ float g_xp[KSPLIT * ROWS * T];   // K-split partials, (row,t)
__device__ float g_yp[ROWS * T];
__device__ __nv_bfloat16 g_xhi[B * T * D];
__device__ __nv_bfloat16 g_xlo[B * T * D];
__device__ __nv_bfloat16 g_mhiT[D * D];     // M^T hi, [c][k]
__device__ __nv_bfloat16 g_mloT[D * D];     // M^T lo, [c][k]

// ============================================================
// Fused prep: blocks [0,3072) split x; [3072,3648) split+transpose M;
// [3648,4032) compute W. All 256-thread blocks.
// ============================================================
constexpr int NB_X = (B * T * D / 2) / 256;          // 3072
constexpr int NB_M = (D / 32) * (D / 32);            // 576
constexpr int NB_W = S * 3;                          // 384

__global__ void __launch_bounds__(256) prep_all(const float* __restrict__ x,
                                                const float* __restrict__ Min,
                                                const float* __restrict__ BC,
                                                const float* __restrict__ Mfil) {
    const int bid = blockIdx.x;
    const int tid = threadIdx.x;
    if (bid < NB_X) {
        int i = (bid * 256 + tid) * 2;
        float v0 = x[i], v1 = x[i + 1];
        __nv_bfloat16 h0 = __float2bfloat16(v0), h1 = __float2bfloat16(v1);
        __nv_bfloat16 l0 = __float2bfloat16(v0 - __bfloat162float(h0));
        __nv_bfloat16 l1 = __float2bfloat16(v1 - __bfloat162float(h1));
        *(__nv_bfloat162*)(g_xhi + i) = __nv_bfloat162(h0, h1);
        *(__nv_bfloat162*)(g_xlo + i) = __nv_bfloat162(l0, l1);
    } else if (bid < NB_X + NB_M) {
        __shared__ float tile[32][33];
        const int m = bid - NB_X;
        const int kb = (m % (D / 32)) * 32, cb = (m / (D / 32)) * 32;
        const int tx = tid & 31, ty = tid >> 5;  // 32 x 8
#pragma unroll
        for (int i = 0; i < 32; i += 8)
            tile[ty + i][tx] = Min[(size_t)(kb + ty + i) * D + cb + tx];
        __syncthreads();
#pragma unroll
        for (int i = 0; i < 32; i += 8) {
            float v = tile[tx][ty + i];
            __nv_bfloat16 h = __float2bfloat16(v);
            __nv_bfloat16 l = __float2bfloat16(v - __bfloat162float(h));
            size_t o = (size_t)(cb + ty + i) * D + kb + tx;
            g_mhiT[o] = h;
            g_mloT[o] = l;
        }
    } else {
        const int m = bid - NB_X - NB_M;
        const int s = m & 127;
        const int c = (m >> 7) * 256 + tid;
        float acc = 0.f;
#pragma unroll
        for (int k = 0; k < HALF; k++) {
            float bsum = BC[s * 2 * HALF + k] + BC[s * 2 * HALF + HALF + k];
            acc = fmaf(bsum, Mfil[k * D + c], acc);
        }
        g_Wt[(size_t)c * S + s] = acc;
    }
}

// ============================================================
// Tensor-core GEMM via mma.sync m16n8k16 bf16, 3-pass split
// (hi*hi + hi*lo + lo*hi). CTA 128c x 64t, warps 4(c) x 2(t),
// warp tile 32x32. K chunk 32. 3-stage cp.async pipeline,
// ONE __syncthreads per chunk.
// ============================================================
__global__ void __launch_bounds__(256, 2) gemm_mma() {
    extern __shared__ char smp[];

    const int tid = threadIdx.x;
    const int wid = tid >> 5;
    const int lane = tid & 31;
    const int wc = wid >> 1;      // 0..3 (c)
    const int wt = wid & 1;       // 0..1 (t)
    const int cbase = blockIdx.x * 128;
    const int tbase = blockIdx.y * 64;
    const int bb = blockIdx.z >> 1;
    const int ks = blockIdx.z & 1;
    const int kbase = ks * KHALF;

    const int a_row = tid >> 2, a_g = tid & 3;
    const int b_row = tid >> 2, b_g = tid & 3;
    const uint32_t sb = smem_u32(smp);
    const uint32_t dA0 = sb + OFF_AH + (a_row * PITCH + a_g * 8) * 2;
    const uint32_t dA1 = sb + OFF_AH + ((a_row + 64) * PITCH + a_g * 8) * 2;
    const uint32_t dL0 = sb + OFF_AL + (a_row * PITCH + a_g * 8) * 2;
    const uint32_t dL1 = sb + OFF_AL + ((a_row + 64) * PITCH + a_g * 8) * 2;
    const uint32_t dBH = sb + OFF_BH + (b_row * PITCH + b_g * 8) * 2;
    const uint32_t dBL = sb + OFF_BL + (b_row * PITCH + b_g * 8) * 2;

    float acc[2][4][4];
#pragma unroll
    for (int i = 0; i < 2; i++)
#pragma unroll
        for (int j = 0; j < 4; j++)
#pragma unroll
            for (int q = 0; q < 4; q++) acc[i][j][q] = 0.f;

    auto issue_loads = [&](int ch, int stg) {
        const int k0 = kbase + ch * 32;
        const size_t a0 = (size_t)(cbase + a_row) * D + k0 + a_g * 8;
        const size_t a1 = (size_t)(cbase + a_row + 64) * D + k0 + a_g * 8;
        const size_t bo = (size_t)(bb * T + tbase + b_row) * D + k0 + b_g * 8;
        const uint32_t so = stg * STAGE;
        cp16(dA0 + so, g_mhiT + a0);
        cp16(dA1 + so, g_mhiT + a1);
        cp16(dL0 + so, g_mloT + a0);
        cp16(dL1 + so, g_mloT + a1);
        cp16(dBH + so, g_xhi + bo);
        cp16(dBL + so, g_xlo + bo);
        cp_commit();
    };

    issue_loads(0, 0);
    issue_loads(1, 1);

    int stg = 0;
    for (int ch = 0; ch < NCHUNK; ch++) {
        cp_wait<1>();      // stage `ch` data resident (group ch retired)
        __syncthreads();   // publish to all warps; also fences stage reuse
        if (ch + 2 < NCHUNK)
            issue_loads(ch + 2, (stg + 2 >= NSTAGE) ? stg + 2 - NSTAGE : stg + 2);
        else
            cp_commit();   // empty group keeps wait-count uniform

        const __nv_bfloat16* Ah = (const __nv_bfloat16*)(smp + stg * STAGE + OFF_AH);
        const __nv_bfloat16* Al = (const __nv_bfloat16*)(smp + stg * STAGE + OFF_AL);
        const __nv_bfloat16* Bh = (const __nv_bfloat16*)(smp + stg * STAGE + OFF_BH);
        const __nv_bfloat16* Bl = (const __nv_bfloat16*)(smp + stg * STAGE + OFF_BL);

#pragma unroll
        for (int ks16 = 0; ks16 < 2; ks16++) {
            uint32_t afh[2][4], afl[2][4], bfh[4][2], bfl[4][2];
            const int ar = (lane & 15);
            const int acol = ks16 * 16 + (lane >> 4) * 8;
#pragma unroll
            for (int mt = 0; mt < 2; mt++) {
                int row = wc * 32 + mt * 16 + ar;
                ldm4(afh[mt], smem_u32(Ah + row * PITCH + acol));
                ldm4(afl[mt], smem_u32(Al + row * PITCH + acol));
            }
            const int bn = (lane & 7) | ((lane & 16) >> 1);
            const int bcol = ks16 * 16 + ((lane >> 3) & 1) * 8;
#pragma unroll
            for (int pr = 0; pr < 2; pr++) {
                int row = wt * 32 + pr * 16 + bn;
                uint32_t r[4];
                ldm4(r, smem_u32(Bh + row * PITCH + bcol));
                bfh[2 * pr][0] = r[0]; bfh[2 * pr][1] = r[1];
                bfh[2 * pr + 1][0] = r[2]; bfh[2 * pr + 1][1] = r[3];
                ldm4(r, smem_u32(Bl + row * PITCH + bcol));
                bfl[2 * pr][0] = r[0]; bfl[2 * pr][1] = r[1];
                bfl[2 * pr + 1][0] = r[2]; bfl[2 * pr + 1][1] = r[3];
            }
#pragma unroll
            for (int mt = 0; mt < 2; mt++)
#pragma unroll
                for (int nt = 0; nt < 4; nt++) {
                    mma16816(acc[mt][nt], afh[mt], bfh[nt]);
                    mma16816(acc[mt][nt], afh[mt], bfl[nt]);
                    mma16816(acc[mt][nt], afl[mt], bfh[nt]);
                }
        }
        stg = (stg + 1 == NSTAGE) ? 0 : stg + 1;
    }

    // epilogue: thread holds (c = base + l/4 (+8), t = nt*8 + 2*(l%4) + {0,1})
    float* outp = g_xp + (size_t)ks * ROWS * T;
#pragma unroll
    for (int mt = 0; mt < 2; mt++) {
        const int cl = wc * 32 + mt * 16 + (lane >> 2);
#pragma unroll
        for (int nt = 0; nt < 4; nt++) {
            const int tl = wt * 32 + nt * 8 + 2 * (lane & 3);
            size_t o0 = (size_t)(bb * D + cbase + cl) * T + tbase + tl;
            *(float2*)(outp + o0) = make_float2(acc[mt][nt][0], acc[mt][nt][1]);
            *(float2*)(outp + o0 + 8 * (size_t)T) = make_float2(acc[mt][nt][2], acc[mt][nt][3]);
        }
    }
}

// ============================================================
// Scan — R7 structure verbatim, 2 K-split partials
// ============================================================
constexpr int SCAN_WARPS = 4;

__global__ void __launch_bounds__(SCAN_WARPS * 32) scan_kernel(const float* __restrict__ Ain) {
    __shared__ float sx[SCAN_WARPS][32];
    __shared__ float sp[SCAN_WARPS][32 * 33];

    const int warp = threadIdx.x >> 5;
    const int lane = threadIdx.x & 31;
    const int row = blockIdx.x * SCAN_WARPS + warp;
    const int c = row % D;

    ull A20 = *(const ull*)(Ain + 2 * lane);
    ull A21 = *(const ull*)(Ain + 64 + 2 * lane);
    const float* Wr = g_Wt + (size_t)c * S;
    ull W20 = *(const ull*)(Wr + 2 * lane);
    ull W21 = *(const ull*)(Wr + 64 + 2 * lane);

    const float* x0 = g_xp + (size_t)row * T;
    const float* x1 = x0 + (size_t)ROWS * T;
    float* yr = g_yp + (size_t)row * T;

    float* sxm = sx[warp];
    float* spm = sp[warp];

    ull h0 = 0ull, h1 = 0ull;

    float xv = x0[lane] + x1[lane];
    for (int t0 = 0; t0 < T; t0 += 32) {
        sxm[lane] = xv;
        __syncwarp();
        if (t0 + 32 < T) {
            int t = t0 + 32 + lane;
            xv = x0[t] + x1[t];
        }
#pragma unroll
        for (int tt = 0; tt < 32; tt++) {
            float xs = sxm[tt];
            ull xx = pack2(xs, xs);
            h0 = ffma2(A20, h0, xx);
            h1 = ffma2(A21, h1, xx);
            ull p = fmul2(h0, W20);
            p = ffma2(h1, W21, p);
            float2 pf = unpack2(p);
            spm[tt * 33 + lane] = pf.x + pf.y;
        }
        __syncwarp();
        const float* col = spm + lane * 33;
        float a0 = 0.f, a1 = 0.f, a2 = 0.f, a3 = 0.f;
#pragma unroll
        for (int l = 0; l < 32; l += 4) {
            a0 += col[l];
            a1 += col[l + 1];
            a2 += col[l + 2];
            a3 += col[l + 3];
        }
        yr[t0 + lane] = (a0 + a1) + (a2 + a3);
        __syncwarp();
    }
}

// ============================================================
// Transpose (row,t) fp32 -> (b,t,c), output f32 on bf16 grid
// ============================================================
__global__ void transpose_kernel(float* __restrict__ out) {
    __shared__ float tile[32][33];
    const int t0 = blockIdx.x * 32;
    const int c0 = blockIdx.y * 32;
    const int b = blockIdx.z;
    const int tx = threadIdx.x, ty = threadIdx.y;
#pragma unroll
    for (int i = 0; i < 32; i += 8)
        tile[ty + i][tx] = g_yp[(size_t)(b * D + c0 + ty + i) * T + t0 + tx];
    __syncthreads();
#pragma unroll
    for (int i = 0; i < 32; i += 8) {
        float v = tile[tx][ty + i];
        out[(size_t)(b * T + t0 + ty + i) * D + c0 + tx] =
            __bfloat162float(__float2bfloat16(v));
    }
}

// ============================================================
extern "C" void kernel_launch(void* const* d_in, const int* in_sizes, int n_in,
                              void* d_out, int out_size) {
    const float* x = nullptr;
    const float *Min = nullptr, *Mfil = nullptr, *A = nullptr, *BC = nullptr;
    for (int i = 0; i < n_in; i++) {
        switch (in_sizes[i]) {  // all five element counts are distinct
            case B * T * D:     x    = (const float*)d_in[i]; break;
            case D * D:         Min  = (const float*)d_in[i]; break;
            case HALF * D:      Mfil = (const float*)d_in[i]; break;
            case S:             A    = (const float*)d_in[i]; break;
            case S * 2 * HALF:  BC   = (const float*)d_in[i]; break;
        }
    }

    cudaFuncSetAttribute(gemm_mma, cudaFuncAttributeMaxDynamicSharedMemorySize, GEMM_SMEM);

    prep_all<<<NB_X + NB_M + NB_W, 256>>>(x, Min, BC, Mfil);
    gemm_mma<<<dim3(D / 128, T / 64, B * KSPLIT), 256, GEMM_SMEM>>>();
    scan_kernel<<<ROWS / SCAN_WARPS, SCAN_WARPS * 32>>>(A);
    transpose_kernel<<<dim3(T / 32, D / 32, B), dim3(32, 8)>>>((float*)d_out);
}